// round 5
// baseline (speedup 1.0000x reference)
#include <cuda_runtime.h>
#include <math.h>

// ---------------------------------------------------------------------------
// HanningTemplateLayer == single fused 80-tap FIR (coeffs computed in-block):
//   out[b,j] = sum_{t=0..79} c[t] * x[b, j+t-40]   (zero padded)
//   c[t]     = sum_w softmax(tw)_w * hann_{2w}[(t-40)+w],  w in {10,20,30,40}
// Two batch rows packed per fma.rn.f32x2 lane.
// Stride-9 padded shared tile: conflict-free strided window reads with pure
// immediate-offset LDS. Coefficient + window both prefetched ~2 iterations
// ahead so no LDS latency is exposed on the FFMA stream.
// ---------------------------------------------------------------------------

#define THREADS 128
#define VOUT    8                  // outputs per thread (per row)
#define RING    12                 // window ring depth (VOUT + 4 prefetch)
#define CPAIRS  2                  // coeff-pair prefetch depth
#define TILE    (THREADS * VOUT)   // 1024 columns per block
#define TAPS    80
#define HALF    40
#define NLOG    (TILE + TAPS)      // 1104 logical float2 entries
#define NQUAD   (NLOG / 4)         // 276
#define NPHYS   (NLOG + NLOG / 8 + 8)
#define LASTWIN (TAPS - 2 + VOUT)  // last window entry consumed (86)

typedef unsigned long long ull;

__global__ __launch_bounds__(THREADS, 8)
void fir80_kernel(const float* __restrict__ x, const float* __restrict__ tw,
                  float* __restrict__ out, int L) {
    __shared__ __align__(16) float2 sx[NPHYS];   // padded, interleaved row pair
    __shared__ __align__(16) float2 sc[TAPS];    // (c,c) duplicated coeffs

    const int tid  = threadIdx.x;
    const int rp   = blockIdx.y;            // row pair index
    const int col0 = blockIdx.x * TILE;

    // ---- tile fill FIRST (get LDGs in flight), quads via LDG.128 ---------
    const float* __restrict__ xa = x + (size_t)(2 * rp) * L;
    const float* __restrict__ xb = xa + L;
    #pragma unroll
    for (int it = 0; it < 3; ++it) {
        int q = tid + it * THREADS;
        if (q < NQUAD) {
            int i = q * 4;                    // logical index, 4-aligned
            int g = col0 - HALF + i;          // 4-aligned (40, L mult of 4)
            float4 a = make_float4(0.f, 0.f, 0.f, 0.f);
            float4 b = make_float4(0.f, 0.f, 0.f, 0.f);
            if (g >= 0 && g + 3 < L) {        // quads are fully in or out
                a = *reinterpret_cast<const float4*>(xa + g);
                b = *reinterpret_cast<const float4*>(xb + g);
            }
            int ph = i + (i >> 3);            // padded physical index
            sx[ph    ] = make_float2(a.x, b.x);
            sx[ph + 1] = make_float2(a.y, b.y);
            sx[ph + 2] = make_float2(a.z, b.z);
            sx[ph + 3] = make_float2(a.w, b.w);
        }
    }

    // ---- coefficients (threads 0..79) overlap the fill latency -----------
    if (tid < TAPS) {
        float w0 = tw[0], w1 = tw[1], w2 = tw[2], w3 = tw[3];
        float m  = fmaxf(fmaxf(w0, w1), fmaxf(w2, w3));
        float e0 = expf(w0 - m), e1 = expf(w1 - m);
        float e2 = expf(w2 - m), e3 = expf(w3 - m);
        float s  = 1.0f / (e0 + e1 + e2 + e3);
        float p[4] = { e0 * s, e1 * s, e2 * s, e3 * s };
        const int widths[4] = { 10, 20, 30, 40 };
        int d = tid - HALF;
        float c = 0.0f;
        #pragma unroll
        for (int i = 0; i < 4; ++i) {
            int w = widths[i];
            int k = d + w;
            if (k >= 0 && k < 2 * w) {
                float h = 0.5f - 0.5f * cosf(6.283185307179586f * (float)k
                                             / (float)(2 * w - 1));
                c = fmaf(p[i], h, c);
            }
        }
        sc[tid] = make_float2(c, c);
    }
    __syncthreads();

    // ---- 80-tap FIR, sliding register ring, immediate-offset LDS ---------
    const ull* __restrict__ P =
        reinterpret_cast<const ull*>(sx) + 9 * tid;      // thread window base
    const ulonglong2* __restrict__ scq =
        reinterpret_cast<const ulonglong2*>(sc);         // 2 taps per LDS.128

    ull acc[VOUT];
    ull win[RING];
    ulonglong2 cbuf[CPAIRS];
    #pragma unroll
    for (int v = 0; v < VOUT; ++v) acc[v] = 0ull;
    #pragma unroll
    for (int j = 0; j < RING; ++j) win[j] = P[j + (j >> 3)];
    #pragma unroll
    for (int q = 0; q < CPAIRS; ++q) cbuf[q] = scq[q];

    // Invariants at tap pair t (q = t/2):
    //   win[(t+i) % RING] == X[lo + t + i],  i in [0, RING)
    //   cbuf[(q+i) % CPAIRS] == (c[2(q+i)], c[2(q+i)+1]),  i in [0, CPAIRS)
    #pragma unroll
    for (int t = 0; t < TAPS; t += 2) {
        const int q = t >> 1;
        ulonglong2 cq = cbuf[q % CPAIRS];
        if (q + CPAIRS < TAPS / 2)
            cbuf[q % CPAIRS] = scq[q + CPAIRS];
        #pragma unroll
        for (int v = 0; v < VOUT; ++v)
            asm("fma.rn.f32x2 %0, %1, %2, %0;"
                : "+l"(acc[v]) : "l"(win[(t + v) % RING]), "l"(cq.x));
        if (t + RING <= LASTWIN)
            win[t % RING] = P[(t + RING) + ((t + RING) >> 3)];
        #pragma unroll
        for (int v = 0; v < VOUT; ++v)
            asm("fma.rn.f32x2 %0, %1, %2, %0;"
                : "+l"(acc[v]) : "l"(win[(t + 1 + v) % RING]), "l"(cq.y));
        if (t + 1 + RING <= LASTWIN)
            win[(t + 1) % RING] = P[(t + 1 + RING) + ((t + 1 + RING) >> 3)];
    }

    // ---- unpack + store (float4 built in place, low live range) ----------
    float* oa = out + (size_t)(2 * rp)     * L + col0 + tid * VOUT;
    float* ob = out + (size_t)(2 * rp + 1) * L + col0 + tid * VOUT;
    #pragma unroll
    for (int v = 0; v < VOUT; v += 4) {
        float4 qa, qb;
        asm("mov.b64 {%0, %1}, %2;" : "=f"(qa.x), "=f"(qb.x) : "l"(acc[v]));
        asm("mov.b64 {%0, %1}, %2;" : "=f"(qa.y), "=f"(qb.y) : "l"(acc[v+1]));
        asm("mov.b64 {%0, %1}, %2;" : "=f"(qa.z), "=f"(qb.z) : "l"(acc[v+2]));
        asm("mov.b64 {%0, %1}, %2;" : "=f"(qa.w), "=f"(qb.w) : "l"(acc[v+3]));
        *reinterpret_cast<float4*>(oa + v) = qa;
        *reinterpret_cast<float4*>(ob + v) = qb;
    }
}

extern "C" void kernel_launch(void* const* d_in, const int* in_sizes, int n_in,
                              void* d_out, int out_size) {
    const float* x  = (const float*)d_in[0];   // [B, L] fp32
    const float* tw = (const float*)d_in[1];   // [4] fp32
    float* out = (float*)d_out;

    const int L = 65536;
    const int B = in_sizes[0] / L;             // 64

    dim3 grid(L / TILE, B / 2);                // (64, 32) = 2048 blocks
    fir80_kernel<<<grid, THREADS>>>(x, tw, out, L);
}

// round 7
// speedup vs baseline: 1.1753x; 1.1753x over previous
#include <cuda_runtime.h>
#include <cuda_bf16.h>
#include <math.h>
#include <cstdint>

// ---------------------------------------------------------------------------
// HanningTemplateLayer as band-aligned Toeplitz GEMM on mma.sync (bf16 hi/lo).
// Per 128-col tile: D[m,n] = sum_k T[m,k] * X[n,k],
//   T[m,k] = c[k-m] (zero outside [0,80)),  X[n,k] = x[n, col0-40+k]
//   out[n, col0+m] = D[m,n]
// Warp w owns m in [16w,16w+16); its band spans k in [16w,16w+96): 6 k-steps.
// A-fragments come straight from a cpair[d]=(c[d],c[d+1]) table (no T in smem).
// 3 products: Ah*Bh + Ah*Bl + Al*Bh  (fp32 accumulate).
// ---------------------------------------------------------------------------

#define THREADS 256
#define TILE_M  128
#define TAPS    80
#define HALF    40
#define L_LEN   65536
#define NB      64           // batch = GEMM N
#define KSEG    208          // 128 + 80 k-extent per tile
#define SROW    264          // uint16 per X row (528B; 528 % 128 == 16 -> conflict-free)
#define SROW2   132          // uint32 stride per X row

// smem byte offsets
#define OFF_CHI   0                     // 128 x u16 bf16(c_hi), offset +24
#define OFF_CLO   256
#define OFF_CPH   512                   // 128 x u32 pair table (offset +16)
#define OFF_CPL   1024
#define OFF_XHI   1536                  // 64 rows x 528B
#define OFF_XLO   (1536 + 64*528)
#define SM_TOTAL  (1536 + 2*64*528)     // 69120 B

__device__ __forceinline__ void mma_bf16(float* d, uint32_t a0, uint32_t a1,
                                         uint32_t a2, uint32_t a3,
                                         uint32_t b0, uint32_t b1) {
    asm("mma.sync.aligned.m16n8k16.row.col.f32.bf16.bf16.f32 "
        "{%0,%1,%2,%3}, {%4,%5,%6,%7}, {%8,%9}, {%0,%1,%2,%3};"
        : "+f"(d[0]), "+f"(d[1]), "+f"(d[2]), "+f"(d[3])
        : "r"(a0), "r"(a1), "r"(a2), "r"(a3), "r"(b0), "r"(b1));
}

__device__ __forceinline__ uint16_t bfbits(__nv_bfloat16 h) {
    return *reinterpret_cast<uint16_t*>(&h);
}

__global__ __launch_bounds__(THREADS, 2)
void hann_mma_kernel(const float* __restrict__ x, const float* __restrict__ tw,
                     float* __restrict__ out) {
    extern __shared__ __align__(16) char smem[];
    uint16_t* chi16 = reinterpret_cast<uint16_t*>(smem + OFF_CHI);
    uint16_t* clo16 = reinterpret_cast<uint16_t*>(smem + OFF_CLO);
    uint32_t* cph   = reinterpret_cast<uint32_t*>(smem + OFF_CPH);
    uint32_t* cpl   = reinterpret_cast<uint32_t*>(smem + OFF_CPL);
    uint16_t* xhi   = reinterpret_cast<uint16_t*>(smem + OFF_XHI);
    uint16_t* xlo   = reinterpret_cast<uint16_t*>(smem + OFF_XLO);

    const int tid  = threadIdx.x;
    const int col0 = blockIdx.x * TILE_M;

    // -- zero coeff scratch (written sparsely later) ---------------------------
    if (tid < 128) { chi16[tid] = 0; clo16[tid] = 0; }

    // -- X tile fill: 64 rows x 52 quads; fp32 -> bf16 hi/lo -------------------
    #pragma unroll
    for (int it = 0; it < 13; ++it) {
        int idx = tid + it * THREADS;            // < 3328
        int row = idx / 52;
        int q   = idx - row * 52;
        int kk  = q * 4;
        int g   = col0 - HALF + kk;              // 4-aligned
        float4 v = make_float4(0.f, 0.f, 0.f, 0.f);
        if (g >= 0 && g + 3 < L_LEN)
            v = *reinterpret_cast<const float4*>(x + (size_t)row * L_LEN + g);
        __nv_bfloat16 h0 = __float2bfloat16(v.x), h1 = __float2bfloat16(v.y);
        __nv_bfloat16 h2 = __float2bfloat16(v.z), h3 = __float2bfloat16(v.w);
        __nv_bfloat16 l0 = __float2bfloat16(v.x - __bfloat162float(h0));
        __nv_bfloat16 l1 = __float2bfloat16(v.y - __bfloat162float(h1));
        __nv_bfloat16 l2 = __float2bfloat16(v.z - __bfloat162float(h2));
        __nv_bfloat16 l3 = __float2bfloat16(v.w - __bfloat162float(h3));
        uint32_t eoff = row * SROW + kk;         // element offset, 4-aligned
        *reinterpret_cast<uint2*>(xhi + eoff) = make_uint2(
            (uint32_t)bfbits(h1) << 16 | bfbits(h0),
            (uint32_t)bfbits(h3) << 16 | bfbits(h2));
        *reinterpret_cast<uint2*>(xlo + eoff) = make_uint2(
            (uint32_t)bfbits(l1) << 16 | bfbits(l0),
            (uint32_t)bfbits(l3) << 16 | bfbits(l2));
    }
    __syncthreads();

    // -- coefficients c[t] (threads 0..79), bf16 hi/lo -------------------------
    if (tid < TAPS) {
        float w0 = tw[0], w1 = tw[1], w2 = tw[2], w3 = tw[3];
        float mx = fmaxf(fmaxf(w0, w1), fmaxf(w2, w3));
        float e0 = expf(w0 - mx), e1 = expf(w1 - mx);
        float e2 = expf(w2 - mx), e3 = expf(w3 - mx);
        float s  = 1.0f / (e0 + e1 + e2 + e3);
        float p[4] = { e0 * s, e1 * s, e2 * s, e3 * s };
        const int widths[4] = { 10, 20, 30, 40 };
        int d = tid - HALF;
        float c = 0.0f;
        #pragma unroll
        for (int i = 0; i < 4; ++i) {
            int w = widths[i], k = d + w;
            if (k >= 0 && k < 2 * w) {
                float h = 0.5f - 0.5f * cosf(6.283185307179586f * (float)k
                                             / (float)(2 * w - 1));
                c = fmaf(p[i], h, c);
            }
        }
        __nv_bfloat16 ch = __float2bfloat16(c);
        __nv_bfloat16 cl = __float2bfloat16(c - __bfloat162float(ch));
        chi16[tid + 24] = bfbits(ch);
        clo16[tid + 24] = bfbits(cl);
    }
    __syncthreads();

    // -- pair tables: cpair[16 + d] = (c[d], c[d+1]), d in [-16, 96) -----------
    if (tid < 112) {
        cph[tid] = (uint32_t)chi16[tid + 9] << 16 | chi16[tid + 8];
        cpl[tid] = (uint32_t)clo16[tid + 9] << 16 | clo16[tid + 8];
    }
    __syncthreads();

    // -- band-aligned MMA: warp w -> m in [16w,16w+16), k in [16w,16w+96) ------
    const int wid = tid >> 5;
    const int lid = tid & 31;
    const int g   = lid >> 2;                 // group (row / n within frag)
    const int t   = lid & 3;                  // thread-in-group
    const int wm0 = wid * 16;

    float d[8][4];
    #pragma unroll
    for (int nf = 0; nf < 8; ++nf)
        #pragma unroll
        for (int r = 0; r < 4; ++r) d[nf][r] = 0.0f;

    #pragma unroll
    for (int s = 0; s < 6; ++s) {
        const int kk = wm0 + 16 * s;
        // A fragments from pair table: idx = 16 + (kk+kofs) - wm0 + 2t - g - rofs
        const int base = 16 + 16 * s + 2 * t - g;
        uint32_t ah0 = cph[base];          // (row g,   k kk..)
        uint32_t ah1 = cph[base - 8];      // (row g+8, k kk..)
        uint32_t ah2 = cph[base + 8];      // (row g,   k kk+8..)
        uint32_t ah3 = cph[base];          // placeholder; fix below
        ah3 = cph[base + 8 - 8];           // (row g+8, k kk+8..) == cph[base]
        uint32_t al0 = cpl[base];
        uint32_t al1 = cpl[base - 8];
        uint32_t al2 = cpl[base + 8];
        uint32_t al3 = cpl[base];

        const int ki = (kk >> 1) + t;      // uint32 index of (kk+2t)
        #pragma unroll
        for (int nf = 0; nf < 8; ++nf) {
            const int n = nf * 8 + g;
            const uint32_t* ph = reinterpret_cast<const uint32_t*>(xhi) + n * SROW2;
            const uint32_t* pl = reinterpret_cast<const uint32_t*>(xlo) + n * SROW2;
            uint32_t bh0 = ph[ki], bh1 = ph[ki + 4];
            uint32_t bl0 = pl[ki], bl1 = pl[ki + 4];
            mma_bf16(d[nf], ah0, ah1, ah2, ah3, bh0, bh1);
            mma_bf16(d[nf], ah0, ah1, ah2, ah3, bl0, bl1);
            mma_bf16(d[nf], al0, al1, al2, al3, bh0, bh1);
        }
    }

    // -- epilogue: D[m,n] -> out[n, col0 + m] ----------------------------------
    const int mg = col0 + wm0 + g;
    #pragma unroll
    for (int nf = 0; nf < 8; ++nf) {
        const size_t n0 = (size_t)(nf * 8 + 2 * t) * L_LEN;
        out[n0 + mg]                      = d[nf][0];
        out[n0 + L_LEN + mg]              = d[nf][1];
        out[n0 + mg + 8]                  = d[nf][2];
        out[n0 + L_LEN + mg + 8]          = d[nf][3];
    }
}

extern "C" void kernel_launch(void* const* d_in, const int* in_sizes, int n_in,
                              void* d_out, int out_size) {
    const float* x  = (const float*)d_in[0];   // [64, 65536] fp32
    const float* tw = (const float*)d_in[1];   // [4] fp32
    float* out = (float*)d_out;

    cudaFuncSetAttribute(hann_mma_kernel,
                         cudaFuncAttributeMaxDynamicSharedMemorySize, SM_TOTAL);
    hann_mma_kernel<<<L_LEN / TILE_M, THREADS, SM_TOTAL>>>(x, tw, out);
}

// round 8
// speedup vs baseline: 1.3159x; 1.1196x over previous
#include <cuda_runtime.h>
#include <cuda_bf16.h>
#include <math.h>
#include <cstdint>

// ---------------------------------------------------------------------------
// HanningTemplateLayer as band-aligned Toeplitz GEMM on mma.sync (bf16 hi/lo).
// Per 128-col tile: D[m,n] = sum_k T[m,k] * X[n,k],
//   T[m,k] = c[k-m] (zero outside [0,80)),  X[n,k] = x[n, col0-40+k]
//   out[n, col0+m] = D[m,n]
// Warp w owns m in [16w,16w+16); its band spans k in [16w,16w+96): 6 k-steps.
// A-fragments come straight from a cpair[d]=(c[d],c[d+1]) table (no T in smem).
// 3 products: Ah*Bh + Ah*Bl + Al*Bh  (fp32 accumulate).
// R8: nf processed in 2 chunks of 4 -> 16 live accumulators, <=85 regs,
//     3 CTAs/SM for latency hiding.
// ---------------------------------------------------------------------------

#define THREADS 256
#define TILE_M  128
#define TAPS    80
#define HALF    40
#define L_LEN   65536
#define SROW    264          // uint16 per X row (528B; stride mod 128 = 16)
#define SROW2   132          // uint32 stride per X row

// smem byte offsets
#define OFF_CHI   0                     // 128 x u16 bf16(c_hi), band at +24
#define OFF_CLO   256
#define OFF_CPH   512                   // 112 x u32 pair table
#define OFF_CPL   1024
#define OFF_XHI   1536                  // 64 rows x 528B
#define OFF_XLO   (1536 + 64*528)
#define SM_TOTAL  (1536 + 2*64*528)     // 69120 B

__device__ __forceinline__ void mma_bf16(float* d, uint32_t a0, uint32_t a1,
                                         uint32_t a2, uint32_t a3,
                                         uint32_t b0, uint32_t b1) {
    asm("mma.sync.aligned.m16n8k16.row.col.f32.bf16.bf16.f32 "
        "{%0,%1,%2,%3}, {%4,%5,%6,%7}, {%8,%9}, {%0,%1,%2,%3};"
        : "+f"(d[0]), "+f"(d[1]), "+f"(d[2]), "+f"(d[3])
        : "r"(a0), "r"(a1), "r"(a2), "r"(a3), "r"(b0), "r"(b1));
}

__device__ __forceinline__ uint16_t bfbits(__nv_bfloat16 h) {
    return *reinterpret_cast<uint16_t*>(&h);
}

__global__ __launch_bounds__(THREADS, 3)
void hann_mma_kernel(const float* __restrict__ x, const float* __restrict__ tw,
                     float* __restrict__ out) {
    extern __shared__ __align__(16) char smem[];
    uint16_t* chi16 = reinterpret_cast<uint16_t*>(smem + OFF_CHI);
    uint16_t* clo16 = reinterpret_cast<uint16_t*>(smem + OFF_CLO);
    uint32_t* cph   = reinterpret_cast<uint32_t*>(smem + OFF_CPH);
    uint32_t* cpl   = reinterpret_cast<uint32_t*>(smem + OFF_CPL);
    uint16_t* xhi   = reinterpret_cast<uint16_t*>(smem + OFF_XHI);
    uint16_t* xlo   = reinterpret_cast<uint16_t*>(smem + OFF_XLO);

    const int tid  = threadIdx.x;
    const int col0 = blockIdx.x * TILE_M;

    // -- zero coeff scratch (band written sparsely later) ----------------------
    if (tid < 128) { chi16[tid] = 0; clo16[tid] = 0; }

    // -- X tile fill: 64 rows x 52 quads; fp32 -> bf16 hi/lo -------------------
    #pragma unroll
    for (int it = 0; it < 13; ++it) {
        int idx = tid + it * THREADS;            // < 3328
        int row = idx / 52;
        int q   = idx - row * 52;
        int kk  = q * 4;
        int g   = col0 - HALF + kk;              // 4-aligned
        float4 v = make_float4(0.f, 0.f, 0.f, 0.f);
        if (g >= 0 && g + 3 < L_LEN)
            v = *reinterpret_cast<const float4*>(x + (size_t)row * L_LEN + g);
        __nv_bfloat16 h0 = __float2bfloat16(v.x), h1 = __float2bfloat16(v.y);
        __nv_bfloat16 h2 = __float2bfloat16(v.z), h3 = __float2bfloat16(v.w);
        __nv_bfloat16 l0 = __float2bfloat16(v.x - __bfloat162float(h0));
        __nv_bfloat16 l1 = __float2bfloat16(v.y - __bfloat162float(h1));
        __nv_bfloat16 l2 = __float2bfloat16(v.z - __bfloat162float(h2));
        __nv_bfloat16 l3 = __float2bfloat16(v.w - __bfloat162float(h3));
        uint32_t eoff = row * SROW + kk;         // element offset, 4-aligned
        *reinterpret_cast<uint2*>(xhi + eoff) = make_uint2(
            (uint32_t)bfbits(h1) << 16 | bfbits(h0),
            (uint32_t)bfbits(h3) << 16 | bfbits(h2));
        *reinterpret_cast<uint2*>(xlo + eoff) = make_uint2(
            (uint32_t)bfbits(l1) << 16 | bfbits(l0),
            (uint32_t)bfbits(l3) << 16 | bfbits(l2));
    }

    // -- coefficients c[t] (threads 0..79), bf16 hi/lo -------------------------
    if (tid < TAPS) {
        float w0 = tw[0], w1 = tw[1], w2 = tw[2], w3 = tw[3];
        float mx = fmaxf(fmaxf(w0, w1), fmaxf(w2, w3));
        float e0 = expf(w0 - mx), e1 = expf(w1 - mx);
        float e2 = expf(w2 - mx), e3 = expf(w3 - mx);
        float s  = 1.0f / (e0 + e1 + e2 + e3);
        float p[4] = { e0 * s, e1 * s, e2 * s, e3 * s };
        const int widths[4] = { 10, 20, 30, 40 };
        int d = tid - HALF;
        float c = 0.0f;
        #pragma unroll
        for (int i = 0; i < 4; ++i) {
            int w = widths[i], k = d + w;
            if (k >= 0 && k < 2 * w) {
                float h = 0.5f - 0.5f * cosf(6.283185307179586f * (float)k
                                             / (float)(2 * w - 1));
                c = fmaf(p[i], h, c);
            }
        }
        __nv_bfloat16 ch = __float2bfloat16(c);
        __nv_bfloat16 cl = __float2bfloat16(c - __bfloat162float(ch));
        chi16[tid + 24] = bfbits(ch);
        clo16[tid + 24] = bfbits(cl);
    }
    __syncthreads();

    // -- pair tables: cpair[16 + d] = (c[d], c[d+1]), d in [-16, 96) -----------
    if (tid < 112) {
        cph[tid] = (uint32_t)chi16[tid + 9] << 16 | chi16[tid + 8];
        cpl[tid] = (uint32_t)clo16[tid + 9] << 16 | clo16[tid + 8];
    }
    __syncthreads();

    // -- band-aligned MMA: warp w -> m in [16w,16w+16), k in [16w,16w+96) ------
    const int wid = tid >> 5;
    const int lid = tid & 31;
    const int g   = lid >> 2;                 // group (row / n within frag)
    const int t   = lid & 3;                  // thread-in-group
    const int wm0 = wid * 16;
    const int mg  = col0 + wm0 + g;

    #pragma unroll
    for (int ch = 0; ch < 2; ++ch) {
        float d[4][4];
        #pragma unroll
        for (int nfi = 0; nfi < 4; ++nfi)
            #pragma unroll
            for (int r = 0; r < 4; ++r) d[nfi][r] = 0.0f;

        #pragma unroll
        for (int s = 0; s < 6; ++s) {
            // A fragments: idx = 16 + (k - m) pair base; ah3 == ah0, al3 == al0
            const int base = 16 + 16 * s + 2 * t - g;
            uint32_t ah0 = cph[base];
            uint32_t ah1 = cph[base - 8];
            uint32_t ah2 = cph[base + 8];
            uint32_t al0 = cpl[base];
            uint32_t al1 = cpl[base - 8];
            uint32_t al2 = cpl[base + 8];

            const int ki = ((wm0 + 16 * s) >> 1) + t;   // uint32 index of k+2t
            #pragma unroll
            for (int nfi = 0; nfi < 4; ++nfi) {
                const int n = (ch * 4 + nfi) * 8 + g;
                const uint32_t* ph = reinterpret_cast<const uint32_t*>(xhi) + n * SROW2;
                const uint32_t* pl = reinterpret_cast<const uint32_t*>(xlo) + n * SROW2;
                uint32_t bh0 = ph[ki], bh1 = ph[ki + 4];
                uint32_t bl0 = pl[ki], bl1 = pl[ki + 4];
                mma_bf16(d[nfi], ah0, ah1, ah2, ah0, bh0, bh1);
                mma_bf16(d[nfi], ah0, ah1, ah2, ah0, bl0, bl1);
                mma_bf16(d[nfi], al0, al1, al2, al0, bh0, bh1);
            }
        }

        // epilogue for this chunk: D[m,n] -> out[n, col0 + m]
        #pragma unroll
        for (int nfi = 0; nfi < 4; ++nfi) {
            const size_t n0 = (size_t)((ch * 4 + nfi) * 8 + 2 * t) * L_LEN;
            out[n0 + mg]             = d[nfi][0];
            out[n0 + L_LEN + mg]     = d[nfi][1];
            out[n0 + mg + 8]         = d[nfi][2];
            out[n0 + L_LEN + mg + 8] = d[nfi][3];
        }
    }
}

extern "C" void kernel_launch(void* const* d_in, const int* in_sizes, int n_in,
                              void* d_out, int out_size) {
    const float* x  = (const float*)d_in[0];   // [64, 65536] fp32
    const float* tw = (const float*)d_in[1];   // [4] fp32
    float* out = (float*)d_out;

    cudaFuncSetAttribute(hann_mma_kernel,
                         cudaFuncAttributeMaxDynamicSharedMemorySize, SM_TOTAL);
    hann_mma_kernel<<<L_LEN / TILE_M, THREADS, SM_TOTAL>>>(x, tw, out);
}